// round 13
// baseline (speedup 1.0000x reference)
#include <cuda_runtime.h>
#include <cuda_fp16.h>
#include <cstdint>

// Tropical (max-times) matvec: out[b, i] = max_j M[i, j] * x[b, j]
// B = 256, n = 2048.
//
// Launch sequence: memsetAsync(d_out, 0xFF) -> prep -> compute.
// prep: packs fp32 M and x into j-packed half2 __device__ buffers.
// compute: persistent 296 CTAs (2/SM), tile 128i x 128b, thread tile 8x8
// (64 half2 accumulators -> 0.5 B LDS per output pair, 2x ILP), BK2=8
// (16 j per stage), 4096 stage-balanced work units.
// Flush: atomicMax on the signed-int bit pattern of the fp32 max (outputs
// are positive -> int order == float order); d_out preset to -1 by memset.

#define NN      2048
#define NB      256
#define NJ2     (NN / 2)             // 1024 half2 per row
#define BM      128
#define BN      128
#define BK2     8                    // half2 per stage (= 16 j)
#define N_TM    (NN / BM)            // 16
#define N_TB    (NB / BN)            // 2
#define N_TILES (N_TM * N_TB)        // 32
#define SPT     (NJ2 / BK2)          // 128 stages per tile
#define NSTAGES (N_TILES * SPT)      // 4096
#define NCTAS   296
#define THREADS 256
#define PITCH   132                  // smem row pitch (half2 units), 16B-aligned

// packed half2 copies of M and x (j-packed), filled by prep_kernel
__device__ unsigned g_Mh[(size_t)NN * NJ2];   // 8.4 MB
__device__ unsigned g_xh[(size_t)NB * NJ2];   // 1.05 MB

__device__ __forceinline__ unsigned h2u(__half2 h) {
    return *reinterpret_cast<unsigned*>(&h);
}
__device__ __forceinline__ __half2 u2h(unsigned u) {
    return *reinterpret_cast<__half2*>(&u);
}

// ---- prep: convert fp32 M and x into j-packed half2 arrays ----
#define M_U4   (NN * NN / 8)         // 524288 uint4 of Mh
#define X_U4   (NB * NN / 8)         // 65536 uint4 of xh
__global__ __launch_bounds__(256, 1)
void prep_kernel(const float* __restrict__ x, const float* __restrict__ M)
{
    const int gid = blockIdx.x * 256 + threadIdx.x;
    const float4* src;
    uint4* dst;
    if (gid < M_U4) {
        src = (const float4*)M + (size_t)gid * 2;
        dst = (uint4*)g_Mh + gid;
    } else if (gid < M_U4 + X_U4) {
        const int g = gid - M_U4;
        src = (const float4*)x + (size_t)g * 2;
        dst = (uint4*)g_xh + g;
    } else {
        return;
    }
    float4 a = src[0], b = src[1];
    uint4 o;
    o.x = h2u(__floats2half2_rn(a.x, a.y));
    o.y = h2u(__floats2half2_rn(a.z, a.w));
    o.z = h2u(__floats2half2_rn(b.x, b.y));
    o.w = h2u(__floats2half2_rn(b.z, b.w));
    *dst = o;
}

__global__ __launch_bounds__(THREADS, 2)
void trop_mm_kernel(int* __restrict__ outw)
{
    __shared__ unsigned Ms[2][BK2][PITCH];   // [buf][j2][i]  8.45 KB
    __shared__ unsigned Xs[2][BK2][PITCH];   // [buf][j2][b]  8.45 KB

    const int tid = threadIdx.x;
    const int tx  = tid & 15;            // b-direction: 16 groups of TN=8
    const int ty  = tid >> 4;            // i-direction: 16 groups of TM=8

    // loader coordinates: per stage, M tile = 128 rows x 2 uint4 (8 half2);
    // X tile identical (BN = 128 rows).
    const int l_row = tid >> 1;          // 0..127
    const int l_q   = tid & 1;           // which uint4 (4 half2) within 8

    // stage-balanced static partition over 4096 stages
    const int s_beg = (int)(((long)blockIdx.x * NSTAGES) / NCTAS);
    const int s_end = (int)(((long)(blockIdx.x + 1) * NSTAGES) / NCTAS);

    uint4 mreg, xreg;

    auto load_stage = [&](int s) {
        const int tile = s >> 7;                 // SPT = 128
        const int kt   = s & 127;                // j2 chunk index
        const int i0   = (tile & (N_TM - 1)) * BM;
        const int b0   = (tile >> 4) * BN;       // N_TM = 16
        mreg = *(const uint4*)(g_Mh + (size_t)(i0 + l_row) * NJ2 + kt * BK2 + l_q * 4);
        xreg = *(const uint4*)(g_xh + (size_t)(b0 + l_row) * NJ2 + kt * BK2 + l_q * 4);
    };

    auto store_stage = [&](int buf) {
        const unsigned* mf = (const unsigned*)&mreg;
        const unsigned* xf = (const unsigned*)&xreg;
        #pragma unroll
        for (int d = 0; d < 4; d++) {
            Ms[buf][l_q * 4 + d][l_row] = mf[d];
            Xs[buf][l_q * 4 + d][l_row] = xf[d];
        }
    };

    // prologue
    load_stage(s_beg);
    store_stage(0);
    __syncthreads();

    const __half2 NEG2 = __float2half2_rn(-65504.0f);
    __half2 acc[8][8];
    #pragma unroll
    for (int a = 0; a < 8; a++)
        #pragma unroll
        for (int c = 0; c < 8; c++)
            acc[a][c] = NEG2;

    int ls = 0;
    for (int s = s_beg; s < s_end; s++, ls++) {
        const int  buf       = ls & 1;
        const bool have_next = (s + 1 < s_end);

        if (have_next)
            load_stage(s + 1);

        #pragma unroll
        for (int kk = 0; kk < BK2; kk++) {
            const uint4 mv0 = *(const uint4*)&Ms[buf][kk][ty * 8];
            const uint4 mv1 = *(const uint4*)&Ms[buf][kk][ty * 8 + 4];
            const uint4 xv0 = *(const uint4*)&Xs[buf][kk][tx * 8];
            const uint4 xv1 = *(const uint4*)&Xs[buf][kk][tx * 8 + 4];

            __half2 m2[8];
            m2[0] = u2h(mv0.x); m2[1] = u2h(mv0.y);
            m2[2] = u2h(mv0.z); m2[3] = u2h(mv0.w);
            m2[4] = u2h(mv1.x); m2[5] = u2h(mv1.y);
            m2[6] = u2h(mv1.z); m2[7] = u2h(mv1.w);
            __half2 x2[8];
            x2[0] = u2h(xv0.x); x2[1] = u2h(xv0.y);
            x2[2] = u2h(xv0.z); x2[3] = u2h(xv0.w);
            x2[4] = u2h(xv1.x); x2[5] = u2h(xv1.y);
            x2[6] = u2h(xv1.z); x2[7] = u2h(xv1.w);

            #pragma unroll
            for (int a = 0; a < 8; a++)
                #pragma unroll
                for (int c = 0; c < 8; c++)
                    acc[a][c] = __hmax2(acc[a][c], __hmul2(m2[a], x2[c]));
        }

        if (have_next)
            store_stage(buf ^ 1);

        // flush at tile boundary or end of range:
        // atomicMax on int bit pattern (outputs positive -> order-preserving)
        if (((s & (SPT - 1)) == SPT - 1) || !have_next) {
            const int tile = s >> 7;
            const int i0   = (tile & (N_TM - 1)) * BM;
            const int b0   = (tile >> 4) * BN;
            #pragma unroll
            for (int c = 0; c < 8; c++) {
                const int b = b0 + tx * 8 + c;
                int* row = outw + (size_t)b * NN + i0 + ty * 8;
                #pragma unroll
                for (int a = 0; a < 8; a++) {
                    float2 f = __half22float2(acc[a][c]);
                    atomicMax(row + a, __float_as_int(fmaxf(f.x, f.y)));
                }
            }
            #pragma unroll
            for (int a = 0; a < 8; a++)
                #pragma unroll
                for (int c = 0; c < 8; c++)
                    acc[a][c] = NEG2;
        }

        __syncthreads();
    }
}

extern "C" void kernel_launch(void* const* d_in, const int* in_sizes, int n_in,
                              void* d_out, int out_size)
{
    // x: [256, 2048] (524288), M: [2048, 2048] (4194304) — detect order defensively
    const float* x;
    const float* M;
    if (in_sizes[0] == NB * NN) { x = (const float*)d_in[0]; M = (const float*)d_in[1]; }
    else                        { x = (const float*)d_in[1]; M = (const float*)d_in[0]; }

    // 0xFFFFFFFF = int -1: smaller than any positive float's bit pattern.
    cudaMemsetAsync(d_out, 0xFF, (size_t)NB * NN * sizeof(int));

    const int prep_blocks = (M_U4 + X_U4 + 255) / 256;   // 2304
    prep_kernel<<<prep_blocks, 256>>>(x, M);

    trop_mm_kernel<<<NCTAS, THREADS>>>((int*)d_out);
}

// round 14
// speedup vs baseline: 1.9699x; 1.9699x over previous
#include <cuda_runtime.h>
#include <cuda_fp16.h>
#include <cstdint>

// Tropical (max-times) matvec: out[b, i] = max_j M[i, j] * x[b, j]
// B = 256, n = 2048.
//
// Launch sequence: memsetAsync(d_out, 0xFF) -> prep -> compute.
// prep: packs fp32 M and x into j-packed half2 __device__ buffers.
// compute: persistent 296 CTAs (2/SM), tile 128i x 64b, thread tile 8x4,
// BK2=16 (32 j per stage), 4096 stage-balanced work units.
// Inner kk loop is register double-buffered: kk+1's smem fragments are
// loaded before kk's math, giving every LDS ~64 issue slots of cover
// (ptxas alone leaves the 29-cyc LDS latency exposed: R12 used only 92/128 regs).
// Flush: atomicMax on the signed-int bit pattern of the fp32 max (outputs
// are positive -> int order == float order); d_out preset to -1 by memset.

#define NN      2048
#define NB      256
#define NJ2     (NN / 2)             // 1024 half2 per row
#define BM      128
#define BN      64
#define BK2     16                   // half2 per stage (= 32 j)
#define N_TM    (NN / BM)            // 16
#define N_TB    (NB / BN)            // 4
#define N_TILES (N_TM * N_TB)        // 64
#define SPT     (NJ2 / BK2)          // 64 stages per tile
#define NSTAGES (N_TILES * SPT)      // 4096
#define NCTAS   296
#define THREADS 256
#define MP      132                  // Ms pitch (half2 units), rows 16B-aligned
#define XP      68                   // Xs pitch

// packed half2 copies of M and x (j-packed), filled by prep_kernel
__device__ unsigned g_Mh[(size_t)NN * NJ2];   // 8.4 MB
__device__ unsigned g_xh[(size_t)NB * NJ2];   // 1.05 MB

__device__ __forceinline__ unsigned h2u(__half2 h) {
    return *reinterpret_cast<unsigned*>(&h);
}
__device__ __forceinline__ __half2 u2h(unsigned u) {
    return *reinterpret_cast<__half2*>(&u);
}

// ---- prep: convert fp32 M and x into j-packed half2 arrays ----
#define M_U4   (NN * NN / 8)         // 524288 uint4 of Mh
#define X_U4   (NB * NN / 8)         // 65536 uint4 of xh
__global__ __launch_bounds__(256, 1)
void prep_kernel(const float* __restrict__ x, const float* __restrict__ M)
{
    const int gid = blockIdx.x * 256 + threadIdx.x;
    const float4* src;
    uint4* dst;
    if (gid < M_U4) {
        src = (const float4*)M + (size_t)gid * 2;
        dst = (uint4*)g_Mh + gid;
    } else if (gid < M_U4 + X_U4) {
        const int g = gid - M_U4;
        src = (const float4*)x + (size_t)g * 2;
        dst = (uint4*)g_xh + g;
    } else {
        return;
    }
    float4 a = src[0], b = src[1];
    uint4 o;
    o.x = h2u(__floats2half2_rn(a.x, a.y));
    o.y = h2u(__floats2half2_rn(a.z, a.w));
    o.z = h2u(__floats2half2_rn(b.x, b.y));
    o.w = h2u(__floats2half2_rn(b.z, b.w));
    *dst = o;
}

__global__ __launch_bounds__(THREADS, 2)
void trop_mm_kernel(int* __restrict__ outw)
{
    __shared__ unsigned Ms[2][BK2][MP];   // [buf][j2][i]  16.9 KB
    __shared__ unsigned Xs[2][BK2][XP];   // [buf][j2][b]   8.7 KB

    const int tid = threadIdx.x;
    const int tx  = tid & 15;            // b-direction: 16 groups of TN=4
    const int ty  = tid >> 4;            // i-direction: 16 groups of TM=8

    // loader coordinates: M tile = 128 rows x 4 uint4 (16 half2); two rounds.
    const int m_row = tid >> 2;          // 0..63 -> rows m_row, m_row + 64
    const int m_q   = tid & 3;           // which uint4 (4 half2) within the 16
    const int x_row = tid >> 2;          // 0..63
    const int x_q   = tid & 3;

    // stage-balanced static partition over 4096 stages
    const int s_beg = (int)(((long)blockIdx.x * NSTAGES) / NCTAS);
    const int s_end = (int)(((long)(blockIdx.x + 1) * NSTAGES) / NCTAS);

    uint4 mreg[2];
    uint4 xreg;

    auto load_stage = [&](int s) {
        const int tile = s >> 6;                 // SPT = 64
        const int kt   = s & 63;                 // j2 chunk index
        const int i0   = (tile & (N_TM - 1)) * BM;
        const int b0   = (tile >> 4) * BN;       // N_TM = 16
        const unsigned* Mg = g_Mh + (size_t)(i0 + m_row) * NJ2 + kt * BK2 + m_q * 4;
        const unsigned* Xg = g_xh + (size_t)(b0 + x_row) * NJ2 + kt * BK2 + x_q * 4;
        mreg[0] = *(const uint4*)(Mg);
        mreg[1] = *(const uint4*)(Mg + (size_t)64 * NJ2);
        xreg    = *(const uint4*)(Xg);
    };

    auto store_stage = [&](int buf) {
        const unsigned* m0 = (const unsigned*)&mreg[0];
        const unsigned* m1 = (const unsigned*)&mreg[1];
        const unsigned* xf = (const unsigned*)&xreg;
        #pragma unroll
        for (int d = 0; d < 4; d++) {
            Ms[buf][m_q * 4 + d][m_row]      = m0[d];
            Ms[buf][m_q * 4 + d][m_row + 64] = m1[d];
            Xs[buf][x_q * 4 + d][x_row]      = xf[d];
        }
    };

    // prologue
    load_stage(s_beg);
    store_stage(0);
    __syncthreads();

    const __half2 NEG2 = __float2half2_rn(-65504.0f);
    __half2 acc[8][4];
    #pragma unroll
    for (int a = 0; a < 8; a++)
        #pragma unroll
        for (int c = 0; c < 4; c++)
            acc[a][c] = NEG2;

    int ls = 0;
    for (int s = s_beg; s < s_end; s++, ls++) {
        const int  buf       = ls & 1;
        const bool have_next = (s + 1 < s_end);

        if (have_next)
            load_stage(s + 1);

        // register double-buffered kk loop: LDS for kk+1 issued before kk's math
        uint4 cm0 = *(const uint4*)&Ms[buf][0][ty * 8];
        uint4 cm1 = *(const uint4*)&Ms[buf][0][ty * 8 + 4];
        uint4 cx4 = *(const uint4*)&Xs[buf][0][tx * 4];

        #pragma unroll
        for (int kk = 0; kk < BK2; kk++) {
            const int kn = (kk + 1 < BK2) ? kk + 1 : kk;   // clamped (last LDS redundant)
            uint4 nm0 = *(const uint4*)&Ms[buf][kn][ty * 8];
            uint4 nm1 = *(const uint4*)&Ms[buf][kn][ty * 8 + 4];
            uint4 nx4 = *(const uint4*)&Xs[buf][kn][tx * 4];

            __half2 m2[8];
            m2[0] = u2h(cm0.x); m2[1] = u2h(cm0.y);
            m2[2] = u2h(cm0.z); m2[3] = u2h(cm0.w);
            m2[4] = u2h(cm1.x); m2[5] = u2h(cm1.y);
            m2[6] = u2h(cm1.z); m2[7] = u2h(cm1.w);
            __half2 x2[4];
            x2[0] = u2h(cx4.x); x2[1] = u2h(cx4.y);
            x2[2] = u2h(cx4.z); x2[3] = u2h(cx4.w);

            #pragma unroll
            for (int a = 0; a < 8; a++)
                #pragma unroll
                for (int c = 0; c < 4; c++)
                    acc[a][c] = __hmax2(acc[a][c], __hmul2(m2[a], x2[c]));

            cm0 = nm0; cm1 = nm1; cx4 = nx4;
        }

        if (have_next)
            store_stage(buf ^ 1);

        // flush at tile boundary or end of range:
        // atomicMax on int bit pattern (outputs positive -> order-preserving)
        if (((s & 63) == 63) || !have_next) {
            const int tile = s >> 6;
            const int i0   = (tile & (N_TM - 1)) * BM;
            const int b0   = (tile >> 4) * BN;
            #pragma unroll
            for (int c = 0; c < 4; c++) {
                const int b = b0 + tx * 4 + c;
                int* row = outw + (size_t)b * NN + i0 + ty * 8;
                #pragma unroll
                for (int a = 0; a < 8; a++) {
                    float2 f = __half22float2(acc[a][c]);
                    atomicMax(row + a, __float_as_int(fmaxf(f.x, f.y)));
                }
            }
            #pragma unroll
            for (int a = 0; a < 8; a++)
                #pragma unroll
                for (int c = 0; c < 4; c++)
                    acc[a][c] = NEG2;
        }

        __syncthreads();
    }
}

extern "C" void kernel_launch(void* const* d_in, const int* in_sizes, int n_in,
                              void* d_out, int out_size)
{
    // x: [256, 2048] (524288), M: [2048, 2048] (4194304) — detect order defensively
    const float* x;
    const float* M;
    if (in_sizes[0] == NB * NN) { x = (const float*)d_in[0]; M = (const float*)d_in[1]; }
    else                        { x = (const float*)d_in[1]; M = (const float*)d_in[0]; }

    // 0xFFFFFFFF = int -1: smaller than any positive float's bit pattern.
    cudaMemsetAsync(d_out, 0xFF, (size_t)NB * NN * sizeof(int));

    const int prep_blocks = (M_U4 + X_U4 + 255) / 256;   // 2304
    prep_kernel<<<prep_blocks, 256>>>(x, M);

    trop_mm_kernel<<<NCTAS, THREADS>>>((int*)d_out);
}